// round 1
// baseline (speedup 1.0000x reference)
#include <cuda_runtime.h>
#include <math.h>

#define BATCH   2
#define SEQLEN  2048
#define DMODEL  2048
#define DSTATE  128
#define DCONV   4
#define HEADDIM 64
#define CHUNK   64
#define DINNER  4096
#define NHEADS  64
#define CONVDIM 4352            // DINNER + 2*DSTATE
#define DINPROJ 8512            // 2*DINNER + 2*DSTATE + NHEADS
#define NTOK    (BATCH*SEQLEN)  // 4096
#define NCHUNK  (SEQLEN/CHUNK)  // 32

// ---------------- device scratch (no cudaMalloc allowed) ----------------
__device__ float g_zx[(size_t)NTOK * DINPROJ];      // in_proj output
__device__ float g_xbc[(size_t)NTOK * CONVDIM];     // conv+silu output
__device__ float g_dtp[NTOK * NHEADS];              // softplus(dt)
__device__ float g_dtA[NTOK * NHEADS];              // A*dt
__device__ float g_states[(size_t)BATCH * NCHUNK * NHEADS * HEADDIM * DSTATE];
__device__ float g_csum[BATCH * NCHUNK * NHEADS];   // per-chunk sum of A*dt
__device__ float g_y[(size_t)NTOK * DINNER];        // SSD output / normed

// ---------------- fp32 SGEMM: 128x64 tile, 256 threads, 8x4 microtile ----
__global__ __launch_bounds__(256) void sgemm_128x64(
    const float* __restrict__ A, const float* __restrict__ B,
    float* __restrict__ C, int M, int N, int K) {
  __shared__ float As[16][132];   // padded: conflict-free scattered stores
  __shared__ float Bs[16][64];
  int tid = threadIdx.x;
  int row0 = blockIdx.y * 128;
  int col0 = blockIdx.x * 64;
  int ar = tid >> 2;              // 0..63 (A row within half-tile)
  int ak = (tid & 3) << 2;        // k offset 0,4,8,12
  int bk = tid >> 4;              // 0..15
  int bn = (tid & 15) << 2;       // 0..60
  int ty = tid >> 4, tx = tid & 15;

  float acc[8][4] = {};
  const float* Aptr  = A + (size_t)(row0 + ar) * K + ak;
  const float* Aptr2 = Aptr + (size_t)64 * K;
  const float* Bptr  = B + (size_t)bk * N + col0 + bn;

  for (int k0 = 0; k0 < K; k0 += 16) {
    float4 a0 = *(const float4*)(Aptr  + k0);
    float4 a1 = *(const float4*)(Aptr2 + k0);
    float4 b0 = *(const float4*)(Bptr + (size_t)k0 * N);
    __syncthreads();
    As[ak+0][ar] = a0.x; As[ak+1][ar] = a0.y; As[ak+2][ar] = a0.z; As[ak+3][ar] = a0.w;
    As[ak+0][ar+64] = a1.x; As[ak+1][ar+64] = a1.y; As[ak+2][ar+64] = a1.z; As[ak+3][ar+64] = a1.w;
    *(float4*)&Bs[bk][bn] = b0;
    __syncthreads();
#pragma unroll
    for (int kk = 0; kk < 16; kk++) {
      float4 x0 = *(const float4*)&As[kk][ty*8];
      float4 x1 = *(const float4*)&As[kk][ty*8+4];
      float4 bb = *(const float4*)&Bs[kk][tx*4];
      float am[8] = {x0.x,x0.y,x0.z,x0.w,x1.x,x1.y,x1.z,x1.w};
      float bm[4] = {bb.x,bb.y,bb.z,bb.w};
#pragma unroll
      for (int i = 0; i < 8; i++)
#pragma unroll
        for (int j = 0; j < 4; j++)
          acc[i][j] += am[i] * bm[j];
    }
  }
#pragma unroll
  for (int i = 0; i < 8; i++) {
    float4 v = make_float4(acc[i][0], acc[i][1], acc[i][2], acc[i][3]);
    *(float4*)&C[(size_t)(row0 + ty*8 + i) * N + col0 + tx*4] = v;
  }
}

// ---------------- dt: softplus + A*dt ----------------
__global__ __launch_bounds__(256) void dt_kernel(
    const float* __restrict__ dt_bias, const float* __restrict__ A_log) {
  int idx = blockIdx.x * 256 + threadIdx.x;
  if (idx >= NTOK * NHEADS) return;
  int h = idx & (NHEADS - 1);
  int tok = idx >> 6;
  float v = g_zx[(size_t)tok * DINPROJ + DINNER + CONVDIM + h] + dt_bias[h];
  float dt = (v > 20.f) ? v : log1pf(expf(v));
  g_dtp[idx] = dt;
  g_dtA[idx] = -expf(A_log[h]) * dt;
}

// ---------------- causal conv1d (width 4) + SiLU ----------------
__global__ __launch_bounds__(256) void conv_kernel(
    const float* __restrict__ conv_w, const float* __restrict__ conv_b) {
  int idx = blockIdx.x * 256 + threadIdx.x;
  if (idx >= NTOK * CONVDIM) return;
  int tok = idx / CONVDIM;
  int ch  = idx - tok * CONVDIM;
  int l   = tok & (SEQLEN - 1);
  float w0 = conv_w[ch*4+0], w1 = conv_w[ch*4+1];
  float w2 = conv_w[ch*4+2], w3 = conv_w[ch*4+3];
  const float* col = &g_zx[(size_t)tok * DINPROJ + DINNER + ch];
  float acc = conv_b[ch] + col[0] * w3;                       // tap at l
  if (l >= 1) acc += col[-(ptrdiff_t)DINPROJ]     * w2;       // l-1
  if (l >= 2) acc += col[-2*(ptrdiff_t)DINPROJ]   * w1;       // l-2
  if (l >= 3) acc += col[-3*(ptrdiff_t)DINPROJ]   * w0;       // l-3
  g_xbc[idx] = acc / (1.f + expf(-acc));                      // silu
}

// ------------- per-chunk local states: S[p][n] = sum_l x*dt*decay * B -----
__global__ __launch_bounds__(256) void chunk_state_kernel() {
  __shared__ float sx[64*64];
  __shared__ float sB[64*128];
  __shared__ float sAc[64];
  __shared__ float sSc[64];
  int h = blockIdx.x, c = blockIdx.y, b = blockIdx.z;
  int tid = threadIdx.x;
  int tok0 = b * SEQLEN + c * CHUNK;

  if (tid < 64) sAc[tid] = g_dtA[(size_t)(tok0 + tid) * NHEADS + h];
  for (int i = tid; i < 64*64; i += 256) {
    int l = i >> 6, p = i & 63;
    sx[i] = g_xbc[(size_t)(tok0 + l) * CONVDIM + h*64 + p];
  }
  for (int i = tid; i < 64*128; i += 256) {
    int l = i >> 7, n = i & 127;
    sB[i] = g_xbc[(size_t)(tok0 + l) * CONVDIM + DINNER + n];
  }
  __syncthreads();
  if (tid == 0) {
    float s = 0.f;
    for (int l = 0; l < 64; l++) { s += sAc[l]; sAc[l] = s; }
    g_csum[(b * NCHUNK + c) * NHEADS + h] = s;
  }
  __syncthreads();
  if (tid < 64)
    sSc[tid] = expf(sAc[63] - sAc[tid]) * g_dtp[(size_t)(tok0 + tid) * NHEADS + h];
  __syncthreads();

  int tx = tid & 15, ty = tid >> 4;
  int p0 = ty * 4, n0 = tx * 8;
  float acc[4][8] = {};
  for (int l = 0; l < 64; l++) {
    float sc = sSc[l];
    float xv[4];
#pragma unroll
    for (int i = 0; i < 4; i++) xv[i] = sx[l*64 + p0 + i] * sc;
#pragma unroll
    for (int j = 0; j < 8; j++) {
      float bv = sB[l*128 + n0 + j];
#pragma unroll
      for (int i = 0; i < 4; i++) acc[i][j] += xv[i] * bv;
    }
  }
  float* S = &g_states[((size_t)(b * NCHUNK + c) * NHEADS + h) * (HEADDIM*DSTATE)];
#pragma unroll
  for (int i = 0; i < 4; i++)
#pragma unroll
    for (int j = 0; j < 8; j++)
      S[(p0 + i) * DSTATE + n0 + j] = acc[i][j];
}

// ------------- sequential cross-chunk scan (in-place: local -> prefix) ----
__global__ __launch_bounds__(256) void scan_kernel() {
  int b = blockIdx.x >> 6, h = blockIdx.x & 63;
  int tid = threadIdx.x;
  __shared__ float sDec[NCHUNK];
  if (tid < NCHUNK) sDec[tid] = expf(g_csum[(b * NCHUNK + tid) * NHEADS + h]);
  __syncthreads();
  for (int e = tid; e < HEADDIM * DSTATE; e += 256) {
    float carry = 0.f;
    for (int c = 0; c < NCHUNK; c++) {
      float* S = &g_states[((size_t)(b * NCHUNK + c) * NHEADS + h) * (HEADDIM*DSTATE) + e];
      float v = *S;
      *S = carry;                  // prefix BEFORE chunk c
      carry = carry * sDec[c] + v;
    }
  }
}

// ------------- Y = diag + off + D*x (per b,chunk,head) -------------------
#define YS 68                      // padded row stride (float4-aligned)
#define SMEM_Y_FLOATS (128*YS*3 + 64*YS*2 + 128)
#define SMEM_Y_BYTES  (SMEM_Y_FLOATS * 4)

__global__ __launch_bounds__(256) void y_kernel(const float* __restrict__ D_param) {
  extern __shared__ float sm[];
  float* sCt = sm;                 // [n=128][l] C transposed
  float* sBt = sCt + 128*YS;       // [n=128][s] B transposed
  float* sSt = sBt + 128*YS;       // [n=128][p] states transposed
  float* sX  = sSt + 128*YS;       // [s=64][p]  raw x
  float* sG  = sX  + 64*YS;        // [s=64][l]  G transposed
  float* sAc = sG  + 64*YS;        // [64]
  float* sDt = sAc + 64;           // [64]
  int h = blockIdx.x, c = blockIdx.y, b = blockIdx.z;
  int tid = threadIdx.x;
  int tok0 = b * SEQLEN + c * CHUNK;

  if (tid < 64) {
    sAc[tid] = g_dtA[(size_t)(tok0 + tid) * NHEADS + h];
    sDt[tid] = g_dtp[(size_t)(tok0 + tid) * NHEADS + h];
  }
  for (int i = tid; i < 64*128; i += 256) {
    int l = i >> 7, n = i & 127;
    const float* src = &g_xbc[(size_t)(tok0 + l) * CONVDIM];
    sBt[n*YS + l] = src[DINNER + n];
    sCt[n*YS + l] = src[DINNER + DSTATE + n];
  }
  const float* Sg = &g_states[((size_t)(b * NCHUNK + c) * NHEADS + h) * (HEADDIM*DSTATE)];
  for (int i = tid; i < 64*128; i += 256) {
    int p = i >> 7, n = i & 127;
    sSt[n*YS + p] = Sg[p * DSTATE + n];
  }
  for (int i = tid; i < 64*64; i += 256) {
    int l = i >> 6, p = i & 63;
    sX[l*YS + p] = g_xbc[(size_t)(tok0 + l) * CONVDIM + h*64 + p];
  }
  __syncthreads();
  if (tid == 0) {
    float s = 0.f;
    for (int l = 0; l < 64; l++) { s += sAc[l]; sAc[l] = s; }
  }
  __syncthreads();

  int tx = tid & 15, ty = tid >> 4;
  int l0 = ty * 4, s0 = tx * 4;
  {
    float acc[4][4] = {};
    for (int n = 0; n < 128; n++) {
      float4 c4 = *(const float4*)&sCt[n*YS + l0];
      float4 b4 = *(const float4*)&sBt[n*YS + s0];
      float cm[4] = {c4.x,c4.y,c4.z,c4.w};
      float bm[4] = {b4.x,b4.y,b4.z,b4.w};
#pragma unroll
      for (int i = 0; i < 4; i++)
#pragma unroll
        for (int j = 0; j < 4; j++)
          acc[i][j] += cm[i] * bm[j];
    }
#pragma unroll
    for (int i = 0; i < 4; i++)
#pragma unroll
      for (int j = 0; j < 4; j++) {
        int l = l0 + i, s = s0 + j;
        float g = 0.f;
        if (s <= l) g = acc[i][j] * expf(sAc[l] - sAc[s]) * sDt[s];
        sG[s*YS + l] = g;          // store transposed
      }
  }
  __syncthreads();

  int p0 = tx * 4;
  float y1[4][4] = {};
  for (int s = 0; s < 64; s++) {
    float4 g4 = *(const float4*)&sG[s*YS + l0];
    float4 x4 = *(const float4*)&sX[s*YS + p0];
    float gm[4] = {g4.x,g4.y,g4.z,g4.w};
    float xm[4] = {x4.x,x4.y,x4.z,x4.w};
#pragma unroll
    for (int i = 0; i < 4; i++)
#pragma unroll
      for (int j = 0; j < 4; j++)
        y1[i][j] += gm[i] * xm[j];
  }
  float y2[4][4] = {};
  for (int n = 0; n < 128; n++) {
    float4 c4 = *(const float4*)&sCt[n*YS + l0];
    float4 s4 = *(const float4*)&sSt[n*YS + p0];
    float cm[4] = {c4.x,c4.y,c4.z,c4.w};
    float smv[4] = {s4.x,s4.y,s4.z,s4.w};
#pragma unroll
    for (int i = 0; i < 4; i++)
#pragma unroll
      for (int j = 0; j < 4; j++)
        y2[i][j] += cm[i] * smv[j];
  }
  float Dh = D_param[h];
#pragma unroll
  for (int i = 0; i < 4; i++) {
    int l = l0 + i;
    float od = expf(sAc[l]);
    float4 out;
    out.x = y1[i][0] + od*y2[i][0] + sX[l*YS + p0+0]*Dh;
    out.y = y1[i][1] + od*y2[i][1] + sX[l*YS + p0+1]*Dh;
    out.z = y1[i][2] + od*y2[i][2] + sX[l*YS + p0+2]*Dh;
    out.w = y1[i][3] + od*y2[i][3] + sX[l*YS + p0+3]*Dh;
    *(float4*)&g_y[(size_t)(tok0 + l) * DINNER + h*64 + p0] = out;
  }
}

// ------------- gated RMSNorm: y = (y*silu(z)) * rrms * w ------------------
__global__ __launch_bounds__(256) void norm_kernel(const float* __restrict__ norm_w) {
  int tok = blockIdx.x;
  const float* z = &g_zx[(size_t)tok * DINPROJ];
  float* y = &g_y[(size_t)tok * DINNER];
  float vals[16];
  float local = 0.f;
#pragma unroll
  for (int i = 0; i < 16; i++) {
    int idx = threadIdx.x + i*256;
    float zv = z[idx];
    float yf = y[idx] * (zv / (1.f + expf(-zv)));
    vals[i] = yf;
    local += yf * yf;
  }
#pragma unroll
  for (int o = 16; o > 0; o >>= 1) local += __shfl_xor_sync(0xffffffffu, local, o);
  __shared__ float wsum[8];
  __shared__ float s_rrms;
  if ((threadIdx.x & 31) == 0) wsum[threadIdx.x >> 5] = local;
  __syncthreads();
  if (threadIdx.x == 0) {
    float t = 0.f;
    for (int w = 0; w < 8; w++) t += wsum[w];
    s_rrms = rsqrtf(t * (1.f / DINNER) + 1e-5f);
  }
  __syncthreads();
  float r = s_rrms;
#pragma unroll
  for (int i = 0; i < 16; i++) {
    int idx = threadIdx.x + i*256;
    y[idx] = vals[i] * r * norm_w[idx];
  }
}

// --------------------------------- launch --------------------------------
extern "C" void kernel_launch(void* const* d_in, const int* in_sizes, int n_in,
                              void* d_out, int out_size) {
  const float* u       = (const float*)d_in[0];
  const float* W_in    = (const float*)d_in[1];
  const float* conv_w  = (const float*)d_in[2];
  const float* conv_b  = (const float*)d_in[3];
  const float* dt_bias = (const float*)d_in[4];
  const float* A_log   = (const float*)d_in[5];
  const float* D_param = (const float*)d_in[6];
  const float* norm_w  = (const float*)d_in[7];
  const float* W_out   = (const float*)d_in[8];
  float* out = (float*)d_out;

  void* zx_ptr; cudaGetSymbolAddress(&zx_ptr, g_zx);
  void* y_ptr;  cudaGetSymbolAddress(&y_ptr,  g_y);
  cudaFuncSetAttribute(y_kernel, cudaFuncAttributeMaxDynamicSharedMemorySize, SMEM_Y_BYTES);

  // 1. in-proj GEMM: [4096,2048] x [2048,8512]
  sgemm_128x64<<<dim3(DINPROJ/64, NTOK/128), 256>>>(u, W_in, (float*)zx_ptr,
                                                    NTOK, DINPROJ, DMODEL);
  // 2. dt: softplus + A*dt
  dt_kernel<<<(NTOK*NHEADS + 255)/256, 256>>>(dt_bias, A_log);
  // 3. causal conv + silu
  conv_kernel<<<(NTOK*CONVDIM + 255)/256, 256>>>(conv_w, conv_b);
  // 4. per-chunk local states
  chunk_state_kernel<<<dim3(NHEADS, NCHUNK, BATCH), 256>>>();
  // 5. cross-chunk scan (local -> prefix states, in place)
  scan_kernel<<<BATCH*NHEADS, 256>>>();
  // 6. Y = diag + off + D*x
  y_kernel<<<dim3(NHEADS, NCHUNK, BATCH), 256, SMEM_Y_BYTES>>>(D_param);
  // 7. gated RMSNorm
  norm_kernel<<<NTOK, 256>>>(norm_w);
  // 8. out-proj GEMM: [4096,4096] x [4096,2048]
  sgemm_128x64<<<dim3(DMODEL/64, NTOK/128), 256>>>((const float*)y_ptr, W_out, out,
                                                   NTOK, DMODEL, DINNER);
}

// round 15
// speedup vs baseline: 1.6392x; 1.6392x over previous
#include <cuda_runtime.h>
#include <cuda_bf16.h>
#include <math.h>
#include <stdint.h>

#define BATCH   2
#define SEQLEN  2048
#define DMODEL  2048
#define DSTATE  128
#define DCONV   4
#define HEADDIM 64
#define CHUNK   64
#define DINNER  4096
#define NHEADS  64
#define CONVDIM 4352            // DINNER + 2*DSTATE
#define DINPROJ 8512            // 2*DINNER + 2*DSTATE + NHEADS
#define NTOK    (BATCH*SEQLEN)  // 4096
#define NCHUNK  (SEQLEN/CHUNK)  // 32

// ---------------- device scratch (no cudaMalloc allowed) ----------------
__device__ float g_zx[(size_t)NTOK * DINPROJ];
__device__ float g_xbc[(size_t)NTOK * CONVDIM];
__device__ float g_dtp[NTOK * NHEADS];
__device__ float g_dtA[NTOK * NHEADS];
__device__ float g_states[(size_t)BATCH * NCHUNK * NHEADS * HEADDIM * DSTATE];
__device__ float g_csum[BATCH * NCHUNK * NHEADS];
__device__ float g_y[(size_t)NTOK * DINNER];

// split-bf16 buffers
__device__ __nv_bfloat16 g_uhi[(size_t)NTOK * DMODEL];
__device__ __nv_bfloat16 g_ulo[(size_t)NTOK * DMODEL];
__device__ __nv_bfloat16 g_WinThi[(size_t)DINPROJ * DMODEL];  // [N,K]
__device__ __nv_bfloat16 g_WinTlo[(size_t)DINPROJ * DMODEL];
__device__ __nv_bfloat16 g_WoutThi[(size_t)DMODEL * DINNER];  // [N,K]
__device__ __nv_bfloat16 g_WoutTlo[(size_t)DMODEL * DINNER];
__device__ __nv_bfloat16 g_yhi[(size_t)NTOK * DINNER];
__device__ __nv_bfloat16 g_ylo[(size_t)NTOK * DINNER];

// ====================== base-target PTX helpers ==========================
__device__ __forceinline__ uint32_t smem_u32(const void* p) {
  uint32_t a;
  asm("{ .reg .u64 t; cvta.to.shared.u64 t, %1; cvt.u32.u64 %0, t; }"
      : "=r"(a) : "l"(p));
  return a;
}
__device__ __forceinline__ void cpasync16(uint32_t dst, const void* src) {
  asm volatile("cp.async.cg.shared.global [%0], [%1], 16;" :: "r"(dst), "l"(src) : "memory");
}
__device__ __forceinline__ void ldsm4(uint32_t* r, uint32_t addr) {
  asm volatile("ldmatrix.sync.aligned.m8n8.x4.shared.b16 {%0,%1,%2,%3}, [%4];"
      : "=r"(r[0]), "=r"(r[1]), "=r"(r[2]), "=r"(r[3]) : "r"(addr));
}
__device__ __forceinline__ void mma16816(float* c, const uint32_t* a, const uint32_t* b) {
  asm volatile("mma.sync.aligned.m16n8k16.row.col.f32.bf16.bf16.f32 "
      "{%0,%1,%2,%3}, {%4,%5,%6,%7}, {%8,%9}, {%0,%1,%2,%3};"
      : "+f"(c[0]), "+f"(c[1]), "+f"(c[2]), "+f"(c[3])
      : "r"(a[0]), "r"(a[1]), "r"(a[2]), "r"(a[3]), "r"(b[0]), "r"(b[1]));
}

// ====================== split / transpose prep ===========================
__global__ __launch_bounds__(256) void split_kernel(
    const float* __restrict__ in, __nv_bfloat16* __restrict__ hi,
    __nv_bfloat16* __restrict__ lo, int n) {
  int i = blockIdx.x * 256 + threadIdx.x;
  if (i >= n) return;
  float x = in[i];
  __nv_bfloat16 h = __float2bfloat16(x);
  hi[i] = h;
  lo[i] = __float2bfloat16(x - __bfloat162float(h));
}

// in [K,N] fp32 -> out [N,K] split bf16
__global__ __launch_bounds__(256) void transpose_split_kernel(
    const float* __restrict__ in, __nv_bfloat16* __restrict__ hi,
    __nv_bfloat16* __restrict__ lo, int K, int N) {
  __shared__ float tile[32][33];
  int n0 = blockIdx.x * 32, k0 = blockIdx.y * 32;
  int tx = threadIdx.x & 31, ty = threadIdx.x >> 5;
  for (int r = ty; r < 32; r += 8)
    tile[r][tx] = in[(size_t)(k0 + r) * N + n0 + tx];
  __syncthreads();
  for (int r = ty; r < 32; r += 8) {
    float x = tile[tx][r];
    size_t o = (size_t)(n0 + r) * K + k0 + tx;
    __nv_bfloat16 h = __float2bfloat16(x);
    hi[o] = h;
    lo[o] = __float2bfloat16(x - __bfloat162float(h));
  }
}

// ====================== mma.sync 3x-bf16 GEMM ============================
// C[M,N] = A[M,K] * B[N,K]^T  (A,B split hi/lo). M%128==0, K%32==0.
#define KSTEP 32
#define AST   40                         // padded smem stride (bf16)
#define TILE_B  (128 * AST * 2)          // 10240 bytes per tile
#define STAGE_B (4 * TILE_B)             // Ahi,Alo,Bhi,Blo
#define GSMEM   (2 * STAGE_B)            // 81920 bytes

__global__ __launch_bounds__(256) void gemm_mma(
    const __nv_bfloat16* __restrict__ Ahi, const __nv_bfloat16* __restrict__ Alo,
    const __nv_bfloat16* __restrict__ Bhi, const __nv_bfloat16* __restrict__ Blo,
    float* __restrict__ C, int M, int N, int K) {
  extern __shared__ __align__(16) char smraw[];
  uint32_t sbase = smem_u32(smraw);
  int tid = threadIdx.x;
  int warp = tid >> 5, lane = tid & 31;
  int wm = warp >> 2, wn = warp & 3;         // 2 x 4 warp grid
  int m0 = blockIdx.y * 128, n0 = blockIdx.x * 128;

  // cp.async chunk assignment: 512 16B-chunks per tile; 2 per thread
  int c0 = tid * 2, c1 = c0 + 1;
  int r0 = c0 >> 2, kg0 = c0 & 3;
  int r1 = c1 >> 2, kg1 = c1 & 3;
  int brow0 = n0 + r0; if (brow0 >= N) brow0 = N - 1;
  int brow1 = n0 + r1; if (brow1 >= N) brow1 = N - 1;

  float acc[4][4][4];
#pragma unroll
  for (int i = 0; i < 4; i++)
#pragma unroll
    for (int j = 0; j < 4; j++)
#pragma unroll
      for (int q = 0; q < 4; q++) acc[i][j][q] = 0.f;

  int nk = K / KSTEP;

#define LOAD_STAGE(st, kt) do {                                                \
    uint32_t sd = sbase + (st) * STAGE_B;                                      \
    int kb = (kt) * KSTEP;                                                     \
    uint32_t d0 = (uint32_t)(r0 * AST + kg0 * 8) * 2;                          \
    uint32_t d1 = (uint32_t)(r1 * AST + kg1 * 8) * 2;                          \
    cpasync16(sd + 0*TILE_B + d0, Ahi + (size_t)(m0 + r0) * K + kb + kg0*8);   \
    cpasync16(sd + 0*TILE_B + d1, Ahi + (size_t)(m0 + r1) * K + kb + kg1*8);   \
    cpasync16(sd + 1*TILE_B + d0, Alo + (size_t)(m0 + r0) * K + kb + kg0*8);   \
    cpasync16(sd + 1*TILE_B + d1, Alo + (size_t)(m0 + r1) * K + kb + kg1*8);   \
    cpasync16(sd + 2*TILE_B + d0, Bhi + (size_t)brow0 * K + kb + kg0*8);       \
    cpasync16(sd + 2*TILE_B + d1, Bhi + (size_t)brow1 * K + kb + kg1*8);       \
    cpasync16(sd + 3*TILE_B + d0, Blo + (size_t)brow0 * K + kb + kg0*8);       \
    cpasync16(sd + 3*TILE_B + d1, Blo + (size_t)brow1 * K + kb + kg1*8);       \
  } while (0)

  LOAD_STAGE(0, 0);
  asm volatile("cp.async.commit_group;" ::: "memory");

  for (int kt = 0; kt < nk; kt++) {
    int st = kt & 1;
    if (kt + 1 < nk) {
      LOAD_STAGE(st ^ 1, kt + 1);
      asm volatile("cp.async.commit_group;" ::: "memory");
      asm volatile("cp.async.wait_group 1;" ::: "memory");
    } else {
      asm volatile("cp.async.wait_group 0;" ::: "memory");
    }
    __syncthreads();

    uint32_t sAhi = sbase + st * STAGE_B;
    uint32_t sAlo = sAhi + TILE_B;
    uint32_t sBhi = sAhi + 2 * TILE_B;
    uint32_t sBlo = sAhi + 3 * TILE_B;

#pragma unroll
    for (int kk = 0; kk < 2; kk++) {
      // B fragments: 2 ldmatrix.x4 per hi/lo, covering ni=0..3
      uint32_t bh[8], bl[8];
#pragma unroll
      for (int p = 0; p < 2; p++) {
        int nrow = wn * 32 + p * 16 + ((lane >> 4) << 3) + (lane & 7);
        int ncol = kk * 16 + ((lane >> 3) & 1) * 8;
        uint32_t off = (uint32_t)(nrow * AST + ncol) * 2;
        ldsm4(&bh[p * 4], sBhi + off);
        ldsm4(&bl[p * 4], sBlo + off);
      }
#pragma unroll
      for (int mi = 0; mi < 4; mi++) {
        int arow = wm * 64 + mi * 16 + (lane & 15);
        int acol = kk * 16 + ((lane >> 4) << 3);
        uint32_t aoff = (uint32_t)(arow * AST + acol) * 2;
        uint32_t ah[4], al[4];
        ldsm4(ah, sAhi + aoff);
        ldsm4(al, sAlo + aoff);
#pragma unroll
        for (int ni = 0; ni < 4; ni++) {
          const uint32_t* bhf = &bh[(ni >> 1) * 4 + (ni & 1) * 2];
          const uint32_t* blf = &bl[(ni >> 1) * 4 + (ni & 1) * 2];
          mma16816(acc[mi][ni], ah, bhf);
          mma16816(acc[mi][ni], ah, blf);
          mma16816(acc[mi][ni], al, bhf);
        }
      }
    }
    __syncthreads();
  }

  // epilogue: acc[mi][ni] -> C
#pragma unroll
  for (int mi = 0; mi < 4; mi++) {
#pragma unroll
    for (int ni = 0; ni < 4; ni++) {
      int row = m0 + wm * 64 + mi * 16 + (lane >> 2);
      int col = n0 + wn * 32 + ni * 8 + (lane & 3) * 2;
      if (col < N) {
        float* d0 = C + (size_t)row * N + col;
        d0[0] = acc[mi][ni][0];
        d0[1] = acc[mi][ni][1];
        float* d1 = C + (size_t)(row + 8) * N + col;
        d1[0] = acc[mi][ni][2];
        d1[1] = acc[mi][ni][3];
      }
    }
  }
}

// ---------------- dt: softplus + A*dt ----------------
__global__ __launch_bounds__(256) void dt_kernel(
    const float* __restrict__ dt_bias, const float* __restrict__ A_log) {
  int idx = blockIdx.x * 256 + threadIdx.x;
  if (idx >= NTOK * NHEADS) return;
  int h = idx & (NHEADS - 1);
  int tok = idx >> 6;
  float v = g_zx[(size_t)tok * DINPROJ + DINNER + CONVDIM + h] + dt_bias[h];
  float dt = (v > 20.f) ? v : log1pf(expf(v));
  g_dtp[idx] = dt;
  g_dtA[idx] = -expf(A_log[h]) * dt;
}

// ---------------- causal conv1d (width 4) + SiLU ----------------
__global__ __launch_bounds__(256) void conv_kernel(
    const float* __restrict__ conv_w, const float* __restrict__ conv_b) {
  int idx = blockIdx.x * 256 + threadIdx.x;
  if (idx >= NTOK * CONVDIM) return;
  int tok = idx / CONVDIM;
  int ch  = idx - tok * CONVDIM;
  int l   = tok & (SEQLEN - 1);
  float w0 = conv_w[ch*4+0], w1 = conv_w[ch*4+1];
  float w2 = conv_w[ch*4+2], w3 = conv_w[ch*4+3];
  const float* col = &g_zx[(size_t)tok * DINPROJ + DINNER + ch];
  float acc = conv_b[ch] + col[0] * w3;
  if (l >= 1) acc += col[-(ptrdiff_t)DINPROJ]   * w2;
  if (l >= 2) acc += col[-2*(ptrdiff_t)DINPROJ] * w1;
  if (l >= 3) acc += col[-3*(ptrdiff_t)DINPROJ] * w0;
  g_xbc[idx] = acc / (1.f + expf(-acc));
}

// ------------- per-chunk local states ------------------------------------
__global__ __launch_bounds__(256) void chunk_state_kernel() {
  __shared__ __align__(16) float sx[64*64];
  __shared__ __align__(16) float sB[64*128];
  __shared__ float sAc[64];
  __shared__ float sSc[64];
  int h = blockIdx.x, c = blockIdx.y, b = blockIdx.z;
  int tid = threadIdx.x;
  int tok0 = b * SEQLEN + c * CHUNK;

  if (tid < 64) sAc[tid] = g_dtA[(size_t)(tok0 + tid) * NHEADS + h];
  for (int i = tid; i < 64*64; i += 256) {
    int l = i >> 6, p = i & 63;
    sx[i] = g_xbc[(size_t)(tok0 + l) * CONVDIM + h*64 + p];
  }
  for (int i = tid; i < 64*128; i += 256) {
    int l = i >> 7, n = i & 127;
    sB[i] = g_xbc[(size_t)(tok0 + l) * CONVDIM + DINNER + n];
  }
  __syncthreads();
  if (tid == 0) {
    float s = 0.f;
    for (int l = 0; l < 64; l++) { s += sAc[l]; sAc[l] = s; }
    g_csum[(b * NCHUNK + c) * NHEADS + h] = s;
  }
  __syncthreads();
  if (tid < 64)
    sSc[tid] = expf(sAc[63] - sAc[tid]) * g_dtp[(size_t)(tok0 + tid) * NHEADS + h];
  __syncthreads();

  int tx = tid & 15, ty = tid >> 4;
  int p0 = ty * 4, n0 = tx * 8;
  float acc[4][8] = {};
  for (int l = 0; l < 64; l++) {
    float sc = sSc[l];
    float4 x4 = *(const float4*)&sx[l*64 + p0];
    float xv[4] = {x4.x*sc, x4.y*sc, x4.z*sc, x4.w*sc};
    float4 b0 = *(const float4*)&sB[l*128 + n0];
    float4 b1 = *(const float4*)&sB[l*128 + n0 + 4];
    float bv[8] = {b0.x,b0.y,b0.z,b0.w,b1.x,b1.y,b1.z,b1.w};
#pragma unroll
    for (int j = 0; j < 8; j++)
#pragma unroll
      for (int i = 0; i < 4; i++) acc[i][j] += xv[i] * bv[j];
  }
  float* S = &g_states[((size_t)(b * NCHUNK + c) * NHEADS + h) * (HEADDIM*DSTATE)];
#pragma unroll
  for (int i = 0; i < 4; i++)
#pragma unroll
    for (int j = 0; j < 8; j++)
      S[(p0 + i) * DSTATE + n0 + j] = acc[i][j];
}

// ------------- sequential cross-chunk scan --------------------------------
__global__ __launch_bounds__(256) void scan_kernel() {
  int b = blockIdx.x >> 6, h = blockIdx.x & 63;
  int tid = threadIdx.x;
  __shared__ float sDec[NCHUNK];
  if (tid < NCHUNK) sDec[tid] = expf(g_csum[(b * NCHUNK + tid) * NHEADS + h]);
  __syncthreads();
  for (int e = tid; e < HEADDIM * DSTATE; e += 256) {
    float carry = 0.f;
    for (int c = 0; c < NCHUNK; c++) {
      float* S = &g_states[((size_t)(b * NCHUNK + c) * NHEADS + h) * (HEADDIM*DSTATE) + e];
      float v = *S;
      *S = carry;
      carry = carry * sDec[c] + v;
    }
  }
}

// ------------- Y = diag + off + D*x ---------------------------------------
#define YS 68
#define SMEM_Y_FLOATS (128*YS*3 + 64*YS*2 + 128)
#define SMEM_Y_BYTES  (SMEM_Y_FLOATS * 4)

__global__ __launch_bounds__(256) void y_kernel(const float* __restrict__ D_param) {
  extern __shared__ float sm[];
  float* sCt = sm;
  float* sBt = sCt + 128*YS;
  float* sSt = sBt + 128*YS;
  float* sX  = sSt + 128*YS;
  float* sG  = sX  + 64*YS;
  float* sAc = sG  + 64*YS;
  float* sDt = sAc + 64;
  int h = blockIdx.x, c = blockIdx.y, b = blockIdx.z;
  int tid = threadIdx.x;
  int tok0 = b * SEQLEN + c * CHUNK;

  if (tid < 64) {
    sAc[tid] = g_dtA[(size_t)(tok0 + tid) * NHEADS + h];
    sDt[tid] = g_dtp[(size_t)(tok0 + tid) * NHEADS + h];
  }
  for (int i = tid; i < 64*128; i += 256) {
    int l = i >> 7, n = i & 127;
    const float* src = &g_xbc[(size_t)(tok0 + l) * CONVDIM];
    sBt[n*YS + l] = src[DINNER + n];
    sCt[n*YS + l] = src[DINNER + DSTATE + n];
  }
  const float* Sg = &g_states[((size_t)(b * NCHUNK + c) * NHEADS + h) * (HEADDIM*DSTATE)];
  for (int i = tid; i < 64*128; i += 256) {
    int p = i >> 7, n = i & 127;
    sSt[n*YS + p] = Sg[p * DSTATE + n];
  }
  for (int i = tid; i < 64*64; i += 256) {
    int l = i >> 6, p = i & 63;
    sX[l*YS + p] = g_xbc[(size_t)(tok0 + l) * CONVDIM + h*64 + p];
  }
  __syncthreads();
  if (tid == 0) {
    float s = 0.f;
    for (int l = 0; l < 64; l++) { s += sAc[l]; sAc[l] = s; }
  }
  __syncthreads();

  int tx = tid & 15, ty = tid >> 4;
  int l0 = ty * 4, s0 = tx * 4;
  {
    float acc[4][4] = {};
    for (int n = 0; n < 128; n++) {
      float4 c4 = *(const float4*)&sCt[n*YS + l0];
      float4 b4 = *(const float4*)&sBt[n*YS + s0];
      float cm[4] = {c4.x,c4.y,c4.z,c4.w};
      float bm[4] = {b4.x,b4.y,b4.z,b4.w};
#pragma unroll
      for (int i = 0; i < 4; i++)
#pragma unroll
        for (int j = 0; j < 4; j++)
          acc[i][j] += cm[i] * bm[j];
    }
#pragma unroll
    for (int i = 0; i < 4; i++)
#pragma unroll
      for (int j = 0; j < 4; j++) {
        int l = l0 + i, s = s0 + j;
        float g = 0.f;
        if (s <= l) g = acc[i][j] * expf(sAc[l] - sAc[s]) * sDt[s];
        sG[s*YS + l] = g;
      }
  }
  __syncthreads();

  int p0 = tx * 4;
  float y1[4][4] = {};
  for (int s = 0; s < 64; s++) {
    float4 g4 = *(const float4*)&sG[s*YS + l0];
    float4 x4 = *(const float4*)&sX[s*YS + p0];
    float gm[4] = {g4.x,g4.y,g4.z,g4.w};
    float xm[4] = {x4.x,x4.y,x4.z,x4.w};
#pragma unroll
    for (int i = 0; i < 4; i++)
#pragma unroll
      for (int j = 0; j < 4; j++)
        y1[i][j] += gm[i] * xm[j];
  }
  float y2[4][4] = {};
  for (int n = 0; n < 128; n++) {
    float4 c4 = *(const float4*)&sCt[n*YS + l0];
    float4 s4 = *(const float4*)&sSt[n*YS + p0];
    float cm[4] = {c4.x,c4.y,c4.z,c4.w};
    float smv[4] = {s4.x,s4.y,s4.z,s4.w};
#pragma unroll
    for (int i = 0; i < 4; i++)
#pragma unroll
      for (int j = 0; j < 4; j++)
        y2[i][j] += cm[i] * smv[j];
  }
  float Dh = D_param[h];
#pragma unroll
  for (int i = 0; i < 4; i++) {
    int l = l0 + i;
    float od = expf(sAc[l]);
    float4 out;
    out.x = y1[i][0] + od*y2[i][0] + sX[l*YS + p0+0]*Dh;
    out.y = y1[i][1] + od*y2[i][1] + sX[l*YS + p0+1]*Dh;
    out.z = y1[i][2] + od*y2[i][2] + sX[l*YS + p0+2]*Dh;
    out.w = y1[i][3] + od*y2[i][3] + sX[l*YS + p0+3]*Dh;
    *(float4*)&g_y[(size_t)(tok0 + l) * DINNER + h*64 + p0] = out;
  }
}

// ------------- gated RMSNorm -> split bf16 for out-proj -------------------
__global__ __launch_bounds__(256) void norm_kernel(const float* __restrict__ norm_w) {
  int tok = blockIdx.x;
  const float* z = &g_zx[(size_t)tok * DINPROJ];
  const float* y = &g_y[(size_t)tok * DINNER];
  float vals[16];
  float local = 0.f;
#pragma unroll
  for (int i = 0; i < 16; i++) {
    int idx = threadIdx.x + i*256;
    float zv = z[idx];
    float yf = y[idx] * (zv / (1.f + expf(-zv)));
    vals[i] = yf;
    local += yf * yf;
  }
#pragma unroll
  for (int o = 16; o > 0; o >>= 1) local += __shfl_xor_sync(0xffffffffu, local, o);
  __shared__ float wsum[8];
  __shared__ float s_rrms;
  if ((threadIdx.x & 31) == 0) wsum[threadIdx.x >> 5] = local;
  __syncthreads();
  if (threadIdx.x == 0) {
    float t = 0.f;
    for (int w = 0; w < 8; w++) t += wsum[w];
    s_rrms = rsqrtf(t * (1.f / DINNER) + 1e-5f);
  }
  __syncthreads();
  float r = s_rrms;
#pragma unroll
  for (int i = 0; i < 16; i++) {
    int idx = threadIdx.x + i*256;
    float v = vals[i] * r * norm_w[idx];
    __nv_bfloat16 hv = __float2bfloat16(v);
    size_t o = (size_t)tok * DINNER + idx;
    g_yhi[o] = hv;
    g_ylo[o] = __float2bfloat16(v - __bfloat162float(hv));
  }
}

// --------------------------------- launch --------------------------------
extern "C" void kernel_launch(void* const* d_in, const int* in_sizes, int n_in,
                              void* d_out, int out_size) {
  const float* u       = (const float*)d_in[0];
  const float* W_in    = (const float*)d_in[1];
  const float* conv_w  = (const float*)d_in[2];
  const float* conv_b  = (const float*)d_in[3];
  const float* dt_bias = (const float*)d_in[4];
  const float* A_log   = (const float*)d_in[5];
  const float* D_param = (const float*)d_in[6];
  const float* norm_w  = (const float*)d_in[7];
  const float* W_out   = (const float*)d_in[8];
  float* out = (float*)d_out;

  void *zx, *uhi, *ulo, *wih, *wil, *woh, *wol, *yhi, *ylo;
  cudaGetSymbolAddress(&zx,  g_zx);
  cudaGetSymbolAddress(&uhi, g_uhi);  cudaGetSymbolAddress(&ulo, g_ulo);
  cudaGetSymbolAddress(&wih, g_WinThi); cudaGetSymbolAddress(&wil, g_WinTlo);
  cudaGetSymbolAddress(&woh, g_WoutThi); cudaGetSymbolAddress(&wol, g_WoutTlo);
  cudaGetSymbolAddress(&yhi, g_yhi);  cudaGetSymbolAddress(&ylo, g_ylo);

  cudaFuncSetAttribute(y_kernel,  cudaFuncAttributeMaxDynamicSharedMemorySize, SMEM_Y_BYTES);
  cudaFuncSetAttribute(gemm_mma,  cudaFuncAttributeMaxDynamicSharedMemorySize, GSMEM);

  // prep: split activations, split+transpose weights
  split_kernel<<<(NTOK*DMODEL + 255)/256, 256>>>(u, (__nv_bfloat16*)uhi, (__nv_bfloat16*)ulo, NTOK*DMODEL);
  transpose_split_kernel<<<dim3(DINPROJ/32, DMODEL/32), 256>>>(W_in, (__nv_bfloat16*)wih, (__nv_bfloat16*)wil, DMODEL, DINPROJ);
  transpose_split_kernel<<<dim3(DMODEL/32, DINNER/32), 256>>>(W_out, (__nv_bfloat16*)woh, (__nv_bfloat16*)wol, DINNER, DMODEL);

  // 1. in-proj GEMM (mma.sync, 3x split-bf16)
  gemm_mma<<<dim3((DINPROJ + 127)/128, NTOK/128), 256, GSMEM>>>(
      (const __nv_bfloat16*)uhi, (const __nv_bfloat16*)ulo,
      (const __nv_bfloat16*)wih, (const __nv_bfloat16*)wil,
      (float*)zx, NTOK, DINPROJ, DMODEL);
  // 2-7. SSD chain
  dt_kernel<<<(NTOK*NHEADS + 255)/256, 256>>>(dt_bias, A_log);
  conv_kernel<<<(NTOK*CONVDIM + 255)/256, 256>>>(conv_w, conv_b);
  chunk_state_kernel<<<dim3(NHEADS, NCHUNK, BATCH), 256>>>();
  scan_kernel<<<BATCH*NHEADS, 256>>>();
  y_kernel<<<dim3(NHEADS, NCHUNK, BATCH), 256, SMEM_Y_BYTES>>>(D_param);
  norm_kernel<<<NTOK, 256>>>(norm_w);
  // 8. out-proj GEMM (mma.sync, 3x split-bf16)
  gemm_mma<<<dim3(DMODEL/128, NTOK/128), 256, GSMEM>>>(
      (const __nv_bfloat16*)yhi, (const __nv_bfloat16*)ylo,
      (const __nv_bfloat16*)woh, (const __nv_bfloat16*)wol,
      out, NTOK, DMODEL, DINNER);
}